// round 16
// baseline (speedup 1.0000x reference)
#include <cuda_runtime.h>
#include <cuda_bf16.h>
#include <cstdint>

// Problem constants:
//   radar_patches, mde_out_patches: (W, B, C=1, H, 1) float32
//   output: (B, 1, H, W) float32
#define PW 1600
#define PB 4
#define PH 900
#define NCOL (PW * PB)              // 6400 columns, each contiguous H floats
#define NV4  (PH / 4)               // 225 float4 per column
#define NBUCK 64
#define BSCALE (64.0f / 82.0f)      // depths in [1,81]
#define SAFE_R 1.2f                 // < bucket width 1.28125 -> +-1 window is exact
#define MAXQ 64                     // queries tracked in 64-bit masks (typ. ~27)
#define WARPS 8

struct WarpState {
    unsigned long long mask[NBUCK];    // bit q set if query q falls in bucket
    unsigned long long omask[NBUCK];   // mask[b-1]|mask[b]|mask[b+1]
    unsigned long long best[MAXQ];     // (|diff|_bits<<10)|mde_idx ; lex-min == argmin w/ first-idx tie
    unsigned long long occ[16];        // 960-bit occupancy (bits >=900 pre-set), 15 used
    float          entryD[MAXQ];
    unsigned short entryY[MAXQ];
    unsigned short plY[MAXQ];
    unsigned char  fb[MAXQ];
    int nfb;
    int pad;
};

__device__ __forceinline__ int bucket_of(float v) {
    int b = __float2int_rd(v * BSCALE);
    return min(NBUCK - 1, max(0, b));
}

// First free slot per reference rule: +1,-1,+2,-2,...  Returns -1 if all full.
__device__ __forceinline__ int find_slot(int by, const unsigned long long* occ) {
    if (!((occ[by >> 6] >> (by & 63)) & 1ull)) return by;
    int du = 1 << 30, up = 0;
    {
        int idx = by + 1;                         // <= 900; bits >=900 pre-occupied
        int wi  = idx >> 6;
        unsigned long long cur = occ[wi] |
            (((idx & 63) != 0) ? ((1ull << (idx & 63)) - 1ull) : 0ull);
        while (cur == ~0ull && wi < 14) { wi++; cur = occ[wi]; }
        if (cur != ~0ull) { up = wi * 64 + __ffsll((long long)~cur) - 1; du = up - by; }
    }
    int dd = 1 << 30, dn = 0;
    if (by > 0) {
        int idx = by - 1;
        int wi  = idx >> 6;
        int bp  = idx & 63;
        unsigned long long cur = occ[wi] |
            ((bp == 63) ? 0ull : (~0ull << (bp + 1)));
        while (cur == ~0ull && wi > 0) { wi--; cur = occ[wi]; }
        if (cur != ~0ull) { dn = wi * 64 + 63 - __clzll((long long)~cur); dd = by - dn; }
    }
    if (du >= (1 << 30) && dd >= (1 << 30)) return -1;   // all 900 occupied
    return (du <= dd) ? up : dn;                          // tie -> + side (checked first)
}

__global__ __launch_bounds__(256) void radar_kernel(
    const float* __restrict__ radar,   // (W,B,H) contiguous per column
    const float* __restrict__ mde,     // (W,B,H)
    float* __restrict__ out)           // (B,1,H,W), pre-zeroed
{
    __shared__ WarpState ws[WARPS];
    const int lane = threadIdx.x & 31;
    const int wid  = threadIdx.x >> 5;
    WarpState& S = ws[wid];

    const int colId = blockIdx.x * WARPS + wid;           // 800*8 = 6400 exactly
    const float* rcol = radar + (size_t)colId * PH;
    const float* mcol = mde   + (size_t)colId * PH;

    // ---- per-warp init ----
    #pragma unroll
    for (int i = lane; i < NBUCK; i += 32) S.mask[i] = 0ull;
    #pragma unroll
    for (int i = lane; i < MAXQ; i += 32) S.best[i] = ~0ull;
    if (lane < 15) S.occ[lane] = (lane == 14) ? ~0xFull : 0ull;  // bits >=900 occupied
    if (lane == 0) S.nfb = 0;
    __syncwarp();

    // ---- load radar (float4, coalesced), compact valid entries ascending y ----
    int base = 0;
    #pragma unroll
    for (int k = 0; k < 8; k++) {
        const int i = k * 32 + lane;
        float4 r = make_float4(0.f, 0.f, 0.f, 0.f);
        if (i < NV4) r = reinterpret_cast<const float4*>(rcol)[i];
        const int c = (r.x != 0.f) + (r.y != 0.f) + (r.z != 0.f) + (r.w != 0.f);
        int incl = c;
        #pragma unroll
        for (int s = 1; s < 32; s <<= 1) {
            int o = __shfl_up_sync(0xffffffffu, incl, s);
            if (lane >= s) incl += o;
        }
        int off = base + incl - c;
        const int y0 = 4 * i;
        if (r.x != 0.f) { if (off < MAXQ) { S.entryD[off] = r.x; S.entryY[off] = (unsigned short)(y0 + 0); atomicOr(&S.mask[bucket_of(r.x)], 1ull << off); } off++; }
        if (r.y != 0.f) { if (off < MAXQ) { S.entryD[off] = r.y; S.entryY[off] = (unsigned short)(y0 + 1); atomicOr(&S.mask[bucket_of(r.y)], 1ull << off); } off++; }
        if (r.z != 0.f) { if (off < MAXQ) { S.entryD[off] = r.z; S.entryY[off] = (unsigned short)(y0 + 2); atomicOr(&S.mask[bucket_of(r.z)], 1ull << off); } off++; }
        if (r.w != 0.f) { if (off < MAXQ) { S.entryD[off] = r.w; S.entryY[off] = (unsigned short)(y0 + 3); atomicOr(&S.mask[bucket_of(r.w)], 1ull << off); } off++; }
        base += __shfl_sync(0xffffffffu, incl, 31);
    }
    const int nvalid = base;                 // uniform across lanes
    if (nvalid == 0) return;                 // column stays all-zero (memset)

    if (nvalid <= MAXQ) {
        // ================= FAST PATH =================
        __syncwarp();
        // pre-OR +-1 bucket windows -> single LDS per mde element
        for (int b = lane; b < NBUCK; b += 32) {
            unsigned long long m = S.mask[b];
            if (b > 0)         m |= S.mask[b - 1];
            if (b < NBUCK - 1) m |= S.mask[b + 1];
            S.omask[b] = m;
        }
        __syncwarp();

        // ---- main pass: each valid mde element updates nearby queries ----
        int mcnt = 0;
        #pragma unroll
        for (int k = 0; k < 8; k++) {
            const int i = k * 32 + lane;
            if (i < NV4) {
                float4 m = __ldg(reinterpret_cast<const float4*>(mcol) + i);
                const int y0 = 4 * i;
                float mv[4] = {m.x, m.y, m.z, m.w};
                #pragma unroll
                for (int j = 0; j < 4; j++) {
                    const float v = mv[j];
                    if (v == 0.f) continue;                  // invalid mde excluded
                    mcnt++;
                    unsigned long long q = S.omask[bucket_of(v)];
                    while (q) {
                        const int e = __ffsll((long long)q) - 1;
                        q &= q - 1;
                        const float diff = fabsf(v - S.entryD[e]);
                        const unsigned long long key =
                            ((unsigned long long)__float_as_uint(diff) << 10) | (unsigned)(y0 + j);
                        if (key < S.best[e]) atomicMin(&S.best[e], key);
                    }
                }
            }
        }
        #pragma unroll
        for (int s = 16; s >= 1; s >>= 1) mcnt += __shfl_xor_sync(0xffffffffu, mcnt, s);
        __syncwarp();

        // ---- resolve; collect rare unsafe queries ----
        for (int e = lane; e < nvalid; e += 32) {
            if (mcnt == 0) {
                S.plY[e] = S.entryY[e];                      // no valid mde -> own y
            } else {
                const unsigned long long kk = S.best[e];
                const bool bad = (kk == ~0ull) ||
                    (__uint_as_float((unsigned)(kk >> 10)) > SAFE_R);
                if (bad) { int p = atomicAdd(&S.nfb, 1); S.fb[p] = (unsigned char)e; }
                else       S.plY[e] = (unsigned short)(kk & 1023u);
            }
        }
        __syncwarp();

        // ---- exact brute-force fallback (P ~ e^-27 per query) ----
        const int nfb = S.nfb;
        for (int f = 0; f < nfb; f++) {
            const int e = S.fb[f];
            const float d = S.entryD[e];
            unsigned long long bk = ~0ull;
            for (int i = lane; i < PH; i += 32) {
                const float v = __ldg(mcol + i);
                if (v != 0.f) {
                    const float diff = fabsf(v - d);
                    const unsigned long long key =
                        ((unsigned long long)__float_as_uint(diff) << 10) | (unsigned)i;
                    if (key < bk) bk = key;
                }
            }
            #pragma unroll
            for (int s = 16; s >= 1; s >>= 1) {
                const unsigned long long o = __shfl_xor_sync(0xffffffffu, bk, s);
                if (o < bk) bk = o;
            }
            if (lane == 0) S.plY[e] = (unsigned short)(bk & 1023u);  // mcnt>0 => valid
        }
        __syncwarp();

        // ---- sequential placement via occupancy bitmask (lane 0) ----
        if (lane == 0) {
            for (int e = 0; e < nvalid; e++) {
                const int by = S.plY[e];
                int f = find_slot(by, S.occ);                // never -1 here (<=64 of 900)
                if (f < 0) f = by;
                S.occ[f >> 6] |= 1ull << (f & 63);
                S.plY[e] = (unsigned short)f;
            }
        }
        __syncwarp();

        // ---- scatter results straight into the (pre-zeroed) output ----
        const int w = colId >> 2, b = colId & 3;
        for (int e = lane; e < nvalid; e += 32)
            out[((size_t)b * PH + S.plY[e]) * PW + w] = S.entryD[e];
    } else {
        // ========== SLOW PATH (nvalid > 64, P ~ 1e-12): exact reference replay ==========
        const int w = colId >> 2, b = colId & 3;
        for (int y = 0; y < PH; y++) {
            float d = (lane == 0) ? __ldg(rcol + y) : 0.f;
            d = __shfl_sync(0xffffffffu, d, 0);
            if (d == 0.f) continue;
            unsigned long long bk = ~0ull;
            for (int i = lane; i < PH; i += 32) {
                const float v = __ldg(mcol + i);
                if (v != 0.f) {
                    const float diff = fabsf(v - d);
                    const unsigned long long key =
                        ((unsigned long long)__float_as_uint(diff) << 10) | (unsigned)i;
                    if (key < bk) bk = key;
                }
            }
            #pragma unroll
            for (int s = 16; s >= 1; s >>= 1) {
                const unsigned long long o = __shfl_xor_sync(0xffffffffu, bk, s);
                if (o < bk) bk = o;
            }
            if (lane == 0) {
                const int by = (bk == ~0ull) ? y : (int)(bk & 1023u);
                int f = find_slot(by, S.occ);
                if (f < 0) f = by;                            // all full -> overwrite
                S.occ[f >> 6] |= 1ull << (f & 63);
                out[((size_t)b * PH + f) * PW + w] = d;       // single-thread, ordered
            }
            __syncwarp();
        }
    }
}

extern "C" void kernel_launch(void* const* d_in, const int* in_sizes, int n_in,
                              void* d_out, int out_size)
{
    const float* radar = (const float*)d_in[0];   // radar_patches (W,B,1,H,1)
    const float* mde   = (const float*)d_in[1];   // mde_out_patches (W,B,1,H,1)
    float* out = (float*)d_out;                   // (B,1,H,W) float32

    cudaMemsetAsync(out, 0, (size_t)out_size * sizeof(float));
    radar_kernel<<<NCOL / WARPS, 256>>>(radar, mde, out);
}